// round 14
// baseline (speedup 1.0000x reference)
#include <cuda_runtime.h>
#include <cuda_bf16.h>
#include <cstdint>

// GAT-style structured attention, M=50000, L=32, F=128.
// R14 = R13 compute/pipeline + persistent grid-stride CTAs: exactly
// 148*5=740 CTAs, each processes ~68 rows (m = bid + k*740). The TMA
// double-buffer pipeline runs across the CTA's whole lifetime: prologue
// (a1 LDGs, mbarrier init, 2-row fill) amortized 8.45x, no wave
// transitions, tail imbalance +-1 row.

#define L_SEG 32
#define F_DIM 128
#define TPB   256
#define WARPS (TPB / 32)          // 8
#define SPW   (L_SEG / WARPS)     // 4 segments per warp
#define ROW_BYTES (L_SEG * F_DIM * 4)   // 16384
#define HALF_BYTES (ROW_BYTES / 2)      // 8192
#define N_CTAS 740                       // 148 SMs x 5 resident

#define MBARRIER_INIT(addr, cnt) \
    asm volatile("mbarrier.init.shared.b64 [%0], %1;" :: "r"(addr), "r"(cnt) : "memory")
#define MBARRIER_EXPECT_TX(addr, bytes) \
    asm volatile("mbarrier.arrive.expect_tx.shared.b64 _, [%0], %1;" :: "r"(addr), "r"(bytes) : "memory")
#define MBARRIER_WAIT_PARITY(addr, parity) do {                                   \
    uint32_t _mb = (addr); uint32_t _p = (parity); uint32_t _done;                \
    asm volatile("{\n\t.reg .pred p;\n\t"                                         \
        "mbarrier.try_wait.parity.acquire.cta.shared::cta.b64 p, [%1], %2;\n\t"   \
        "selp.b32 %0, 1, 0, p;\n\t}"                                              \
        : "=r"(_done) : "r"(_mb), "r"(_p) : "memory");                            \
    if (!_done) {                                                                 \
        asm volatile("{\n\t.reg .pred P1;\n\t"                                    \
            "WL_%=:\n\t"                                                          \
            "mbarrier.try_wait.parity.acquire.cta.shared::cta.b64 P1, [%0], %1, 0x989680;\n\t" \
            "@P1 bra.uni WD_%=;\n\t"                                              \
            "bra.uni WL_%=;\n\t"                                                  \
            "WD_%=:\n\t}"                                                         \
            :: "r"(_mb), "r"(_p) : "memory");                                     \
    }                                                                             \
} while (0)

__device__ __forceinline__ void bulk_ldgsts(uint32_t smem_dst, const void* gsrc,
                                            uint32_t bytes, uint32_t mbar) {
    asm volatile(
        "cp.async.bulk.shared::cluster.global.mbarrier::complete_tx::bytes "
        "[%0], [%1], %2, [%3];"
        :: "r"(smem_dst), "l"(gsrc), "r"(bytes), "r"(mbar) : "memory");
}

// stage one row as two 8KB bulk copies (2x request MLP)
__device__ __forceinline__ void stage_row(uint32_t smem_dst, const float* gsrc,
                                          uint32_t mbar) {
    MBARRIER_EXPECT_TX(mbar, (uint32_t)ROW_BYTES);
    bulk_ldgsts(smem_dst, gsrc, (uint32_t)HALF_BYTES, mbar);
    bulk_ldgsts(smem_dst + (uint32_t)HALF_BYTES,
                (const char*)gsrc + HALF_BYTES, (uint32_t)HALF_BYTES, mbar);
}

__global__ __launch_bounds__(TPB, 5)
void gat_row_kernel(const float* __restrict__ x,
                    const float* __restrict__ a,
                    float* __restrict__ out,
                    int M)
{
    const int tid  = threadIdx.x;
    const int w    = tid >> 5;
    const int lane = tid & 31;
    const int G    = gridDim.x;            // row stride (=N_CTAS)
    const int m0   = blockIdx.x;
    if (m0 >= M) return;

    __shared__ alignas(16) float4 stage[2][TPB * SPW];   // 2 x 16KB
    __shared__ alignas(8) unsigned long long mbar[2];
    __shared__ float  s_nbr[L_SEG];
    __shared__ float  s_msk[L_SEG];
    __shared__ float  warp_self[WARPS];                  // float4-aligned
    __shared__ float4 hp[WARPS * 32];

    const uint32_t mbar_u32  = (uint32_t)__cvta_generic_to_shared(&mbar[0]);
    const uint32_t stage_u32 = (uint32_t)__cvta_generic_to_shared(&stage[0][0]);

    if (tid == 0) {
        MBARRIER_INIT(mbar_u32, 1);
        MBARRIER_INIT(mbar_u32 + 8, 1);
    }
    __syncthreads();   // mbarrier init visible

    // ---- prologue: stage rows m0 and m0+G (issuer: warp 7 lane 0) ----
    if (tid == TPB - 32) {
        stage_row(stage_u32, x + (size_t)m0 * (L_SEG * F_DIM), mbar_u32);
        if (m0 + G < M)
            stage_row(stage_u32 + (uint32_t)ROW_BYTES,
                      x + (size_t)(m0 + G) * (L_SEG * F_DIM), mbar_u32 + 8);
    }

    // ---- per-thread weight slices (LDG latency overlaps the TMAs) ----
    const float4* __restrict__ a1p = (const float4*)a;
    float4 a1r[SPW];
#pragma unroll
    for (int j = 0; j < SPW; ++j)
        a1r[j] = __ldg(a1p + (w * SPW + j) * (F_DIM / 4) + lane);
    const float4 a2 = __ldg(((const float4*)(a + L_SEG * F_DIM)) + lane);

    const bool bb4 = (lane & 16) != 0;
    const bool bb3 = (lane & 8)  != 0;
    const bool bb2 = (lane & 4)  != 0;

    int ph0 = 0, ph1 = 0;
    int b = 0;   // current buffer

#pragma unroll 1
    for (int m = m0; m < M; m += G, b ^= 1) {

        // ---- wait for row m's data ----
        if (b == 0) { MBARRIER_WAIT_PARITY(mbar_u32,     ph0); ph0 ^= 1; }
        else        { MBARRIER_WAIT_PARITY(mbar_u32 + 8, ph1); ph1 ^= 1; }

        // ---- pull this row from smem (linear layout, conflict-free) ----
        float4 v[SPW];
#pragma unroll
        for (int j = 0; j < SPW; ++j)
            v[j] = stage[b][(w * SPW + j) * (F_DIM / 4) + lane];

        // ---- phase A: lane-local dots ----
        float sn[SPW], mk[SPW];
        float self_part = 0.f;
#pragma unroll
        for (int j = 0; j < SPW; ++j) {
            const float4 vv = v[j];
            mk[j] = (vv.x + vv.y) + (vv.z + vv.w);
            sn[j] = vv.x * a2.x + vv.y * a2.y + vv.z * a2.z + vv.w * a2.w;
            self_part += vv.x * a1r[j].x + vv.y * a1r[j].y
                       + vv.z * a1r[j].z + vv.w * a1r[j].w;
        }

        // ---- 8-value multi-butterfly (idx = lane>>2 at the end) ----
        float t0, t1, t2, t3;
        {
            const float s0 = bb4 ? sn[0] : mk[0];
            const float s1 = bb4 ? sn[1] : mk[1];
            const float s2 = bb4 ? sn[2] : mk[2];
            const float s3 = bb4 ? sn[3] : mk[3];
            t0 = (bb4 ? mk[0] : sn[0]) + __shfl_xor_sync(0xffffffffu, s0, 16);
            t1 = (bb4 ? mk[1] : sn[1]) + __shfl_xor_sync(0xffffffffu, s1, 16);
            t2 = (bb4 ? mk[2] : sn[2]) + __shfl_xor_sync(0xffffffffu, s2, 16);
            t3 = (bb4 ? mk[3] : sn[3]) + __shfl_xor_sync(0xffffffffu, s3, 16);
        }
        float u0, u1;
        {
            const float s0 = bb3 ? t0 : t2;
            const float s1 = bb3 ? t1 : t3;
            u0 = (bb3 ? t2 : t0) + __shfl_xor_sync(0xffffffffu, s0, 8);
            u1 = (bb3 ? t3 : t1) + __shfl_xor_sync(0xffffffffu, s1, 8);
        }
        float c;
        {
            const float s0 = bb2 ? u0 : u1;
            c = (bb2 ? u1 : u0) + __shfl_xor_sync(0xffffffffu, s0, 4);
        }
        c += __shfl_xor_sync(0xffffffffu, c, 2);
        c += __shfl_xor_sync(0xffffffffu, c, 1);

        // self-score: plain 5-level tree (independent chain)
#pragma unroll
        for (int o = 16; o; o >>= 1)
            self_part += __shfl_xor_sync(0xffffffffu, self_part, o);

        if ((lane & 3) == 0) {
            const int idx = lane >> 2;            // 0..7
            if (idx < 4) s_nbr[w * SPW + idx] = c;
            else         s_msk[w * SPW + (idx - 4)] = c;
        }
        if (lane == 0) warp_self[w] = self_part;
        __syncthreads();
        // ^ also proves every warp has drained stage[b]: reusable now.

        // ---- early re-issue: row m+2G into buffer b ----
        if (tid == TPB - 32 && m + 2 * G < M)
            stage_row(stage_u32 + (uint32_t)(b * ROW_BYTES),
                      x + (size_t)(m + 2 * G) * (L_SEG * F_DIM),
                      mbar_u32 + (uint32_t)(b * 8));

        // ---- phase B: softmax over 32 segments (no max-subtraction) ----
        const float4 ws0 = ((const float4*)warp_self)[0];
        const float4 ws1 = ((const float4*)warp_self)[1];
        const float s_self = ((ws0.x + ws0.y) + (ws0.z + ws0.w))
                           + ((ws1.x + ws1.y) + (ws1.z + ws1.w));
        const float z = s_self + s_nbr[lane];
        float e = (z >= 0.0f) ? z : 0.2f * z;
        e = (s_msk[lane] != 0.0f) ? e : -1e30f;
        const float ex = __expf(e);               // masked -> 0
        float sum = ex;
#pragma unroll
        for (int o = 16; o; o >>= 1)
            sum += __shfl_xor_sync(0xffffffffu, sum, o);
        const float att_lane = ex / sum;

        // ---- attention-weighted recombination from registers ----
        float4 h = make_float4(0.f, 0.f, 0.f, 0.f);
#pragma unroll
        for (int j = 0; j < SPW; ++j) {
            const float aL = __shfl_sync(0xffffffffu, att_lane, w * SPW + j);
            h.x += aL * v[j].x;
            h.y += aL * v[j].y;
            h.z += aL * v[j].z;
            h.w += aL * v[j].w;
        }

        hp[w * 32 + lane] = h;
        __syncthreads();

        // ---- cross-warp reduce (warp 0) + epilogue + store ----
        if (w == 0) {
            float4 acc = hp[lane];
#pragma unroll
            for (int i = 1; i < WARPS; ++i) {
                const float4 t = hp[i * 32 + lane];
                acc.x += t.x; acc.y += t.y; acc.z += t.z; acc.w += t.w;
            }
            acc.x = (acc.x > 0.f) ? acc.x : (__expf(acc.x) - 1.0f);
            acc.y = (acc.y > 0.f) ? acc.y : (__expf(acc.y) - 1.0f);
            acc.z = (acc.z > 0.f) ? acc.z : (__expf(acc.z) - 1.0f);
            acc.w = (acc.w > 0.f) ? acc.w : (__expf(acc.w) - 1.0f);
            ((float4*)(out + (size_t)m * F_DIM))[lane] = acc;
        }
    }
}

extern "C" void kernel_launch(void* const* d_in, const int* in_sizes, int n_in,
                              void* d_out, int out_size)
{
    const float* x = (const float*)d_in[0];
    const float* a = (const float*)d_in[1];
    float* out = (float*)d_out;

    // Shapes from element counts (capture-safe):
    //   in_sizes[0] = M*L*F, in_sizes[1] = F*(L+1), out_size = M*F
    const long long total = in_sizes[0];
    const int L = (int)(total / (long long)out_size);      // 32
    const int F = in_sizes[1] / (L + 1);                   // 128
    const int M = out_size / F;                            // 50000
    (void)L; (void)F;

    const int grid = (M < N_CTAS) ? M : N_CTAS;
    gat_row_kernel<<<grid, TPB>>>(x, a, out, M);
}

// round 15
// speedup vs baseline: 1.1574x; 1.1574x over previous
#include <cuda_runtime.h>
#include <cuda_bf16.h>
#include <cstdint>

// GAT-style structured attention, M=50000, L=32, F=128.
// R15 = R13 base (TMA 2x8KB staging, early re-issue, ROWS=8)
// + packed f32x2 math (FFMA2/FADD2 via PTX, sm_103a): self-dot,
//   recombination and warp0 epilogue reduction run on 64-bit packed pairs
//   loaded directly from smem (no repack cost);
// + row loop unrolled 2x so buffer/phase selection is compile-time.
// Rationale: per-row time (2.07us) > per-row chip memory time (1.5us);
// issue=70% -> the loop is instruction-limited, so cut instructions.

#define L_SEG 32
#define F_DIM 128
#define TPB   256
#define WARPS (TPB / 32)          // 8
#define SPW   (L_SEG / WARPS)     // 4 segments per warp
#define ROWS_PER_CTA 8
#define ROW_BYTES (L_SEG * F_DIM * 4)   // 16384
#define HALF_BYTES (ROW_BYTES / 2)      // 8192

typedef unsigned long long u64t;

#define MBARRIER_INIT(addr, cnt) \
    asm volatile("mbarrier.init.shared.b64 [%0], %1;" :: "r"(addr), "r"(cnt) : "memory")
#define MBARRIER_EXPECT_TX(addr, bytes) \
    asm volatile("mbarrier.arrive.expect_tx.shared.b64 _, [%0], %1;" :: "r"(addr), "r"(bytes) : "memory")
#define MBARRIER_WAIT_PARITY(addr, parity) do {                                   \
    uint32_t _mb = (addr); uint32_t _p = (parity); uint32_t _done;                \
    asm volatile("{\n\t.reg .pred p;\n\t"                                         \
        "mbarrier.try_wait.parity.acquire.cta.shared::cta.b64 p, [%1], %2;\n\t"   \
        "selp.b32 %0, 1, 0, p;\n\t}"                                              \
        : "=r"(_done) : "r"(_mb), "r"(_p) : "memory");                            \
    if (!_done) {                                                                 \
        asm volatile("{\n\t.reg .pred P1;\n\t"                                    \
            "WL_%=:\n\t"                                                          \
            "mbarrier.try_wait.parity.acquire.cta.shared::cta.b64 P1, [%0], %1, 0x989680;\n\t" \
            "@P1 bra.uni WD_%=;\n\t"                                              \
            "bra.uni WL_%=;\n\t"                                                  \
            "WD_%=:\n\t}"                                                         \
            :: "r"(_mb), "r"(_p) : "memory");                                     \
    }                                                                             \
} while (0)

__device__ __forceinline__ void bulk_ldgsts(uint32_t smem_dst, const void* gsrc,
                                            uint32_t bytes, uint32_t mbar) {
    asm volatile(
        "cp.async.bulk.shared::cluster.global.mbarrier::complete_tx::bytes "
        "[%0], [%1], %2, [%3];"
        :: "r"(smem_dst), "l"(gsrc), "r"(bytes), "r"(mbar) : "memory");
}

__device__ __forceinline__ void stage_row(uint32_t smem_dst, const float* gsrc,
                                          uint32_t mbar) {
    MBARRIER_EXPECT_TX(mbar, (uint32_t)ROW_BYTES);
    bulk_ldgsts(smem_dst, gsrc, (uint32_t)HALF_BYTES, mbar);
    bulk_ldgsts(smem_dst + (uint32_t)HALF_BYTES,
                (const char*)gsrc + HALF_BYTES, (uint32_t)HALF_BYTES, mbar);
}

// ---- packed f32x2 helpers (sm_103a FFMA2/FADD2/FMUL2) ----
__device__ __forceinline__ u64t pk2(float lo, float hi) {
    u64t r; asm("mov.b64 %0, {%1, %2};" : "=l"(r) : "f"(lo), "f"(hi)); return r;
}
__device__ __forceinline__ void upk2(u64t p, float& lo, float& hi) {
    asm("mov.b64 {%0, %1}, %2;" : "=f"(lo), "=f"(hi) : "l"(p));
}
__device__ __forceinline__ u64t fma2(u64t a, u64t b, u64t c) {
    u64t d; asm("fma.rn.f32x2 %0, %1, %2, %3;" : "=l"(d) : "l"(a), "l"(b), "l"(c)); return d;
}
__device__ __forceinline__ u64t mul2(u64t a, u64t b) {
    u64t d; asm("mul.rn.f32x2 %0, %1, %2;" : "=l"(d) : "l"(a), "l"(b)); return d;
}
__device__ __forceinline__ u64t add2(u64t a, u64t b) {
    u64t d; asm("add.rn.f32x2 %0, %1, %2;" : "=l"(d) : "l"(a), "l"(b)); return d;
}

__global__ __launch_bounds__(TPB, 5)
void gat_row_kernel(const float* __restrict__ x,
                    const float* __restrict__ a,
                    float* __restrict__ out,
                    int M)
{
    const int tid  = threadIdx.x;
    const int w    = tid >> 5;
    const int lane = tid & 31;
    const int m0   = blockIdx.x * ROWS_PER_CTA;
    if (m0 >= M) return;
    const int rows = (M - m0 < ROWS_PER_CTA) ? (M - m0) : ROWS_PER_CTA;

    __shared__ alignas(16) float4 stage[2][TPB * SPW];   // 2 x 16KB
    __shared__ alignas(8) unsigned long long mbar[2];
    __shared__ float  s_nbr[L_SEG];
    __shared__ float  s_msk[L_SEG];
    __shared__ float  warp_self[WARPS];                  // float4-aligned
    __shared__ alignas(16) u64t hp[WARPS * 32 * 2];      // packed float4 per (w,lane)

    const uint32_t mbar_u32  = (uint32_t)__cvta_generic_to_shared(&mbar[0]);
    const uint32_t stage_u32 = (uint32_t)__cvta_generic_to_shared(&stage[0][0]);

    if (tid == 0) {
        MBARRIER_INIT(mbar_u32, 1);
        MBARRIER_INIT(mbar_u32 + 8, 1);
    }
    __syncthreads();   // mbarrier init visible

    // ---- prologue: stage rows 0 and 1 (issuer: warp 7 lane 0) ----
    if (tid == TPB - 32) {
        stage_row(stage_u32, x + (size_t)m0 * (L_SEG * F_DIM), mbar_u32);
        if (rows > 1)
            stage_row(stage_u32 + (uint32_t)ROW_BYTES,
                      x + (size_t)(m0 + 1) * (L_SEG * F_DIM), mbar_u32 + 8);
    }

    // ---- per-thread weight slices, pre-packed (LDG overlaps the TMAs) ----
    const float4* __restrict__ a1p = (const float4*)a;
    u64t a1lo[SPW], a1hi[SPW];
#pragma unroll
    for (int j = 0; j < SPW; ++j) {
        const float4 t = __ldg(a1p + (w * SPW + j) * (F_DIM / 4) + lane);
        a1lo[j] = pk2(t.x, t.y); a1hi[j] = pk2(t.z, t.w);
    }
    u64t a2lo, a2hi;
    {
        const float4 t = __ldg(((const float4*)(a + L_SEG * F_DIM)) + lane);
        a2lo = pk2(t.x, t.y); a2hi = pk2(t.z, t.w);
    }

    const bool bb4 = (lane & 16) != 0;
    const bool bb3 = (lane & 8)  != 0;
    const bool bb2 = (lane & 4)  != 0;

    int ph0 = 0, ph1 = 0;

#pragma unroll 2
    for (int r = 0; r < rows; ++r) {
        const int m = m0 + r;
        const int b = r & 1;   // compile-time under unroll 2

        // ---- wait for row r's data ----
        if (b == 0) { MBARRIER_WAIT_PARITY(mbar_u32,     ph0); ph0 ^= 1; }
        else        { MBARRIER_WAIT_PARITY(mbar_u32 + 8, ph1); ph1 ^= 1; }

        // ---- pull this row from smem as packed pairs (same LDS.128) ----
        u64t vlo[SPW], vhi[SPW];
#pragma unroll
        for (int j = 0; j < SPW; ++j) {
            const ulonglong2 t = ((const ulonglong2*)&stage[b][0])
                                     [(w * SPW + j) * (F_DIM / 4) + lane];
            vlo[j] = t.x; vhi[j] = t.y;
        }

        // ---- phase A: lane-local dots (packed) ----
        float sn[SPW], mk[SPW];
        u64t sp2 = 0;   // packed self accumulator (0.0f pair)
#pragma unroll
        for (int j = 0; j < SPW; ++j) {
            u64t sn2 = mul2(vlo[j], a2lo);
            sn2 = fma2(vhi[j], a2hi, sn2);
            float snl, snh; upk2(sn2, snl, snh);
            sn[j] = snl + snh;

            const u64t mk2 = add2(vlo[j], vhi[j]);
            float mkl, mkh; upk2(mk2, mkl, mkh);
            mk[j] = mkl + mkh;

            sp2 = fma2(vlo[j], a1lo[j], sp2);
            sp2 = fma2(vhi[j], a1hi[j], sp2);
        }
        float spl, sph; upk2(sp2, spl, sph);
        float self_part = spl + sph;

        // ---- 8-value multi-butterfly (idx = lane>>2 at the end) ----
        float t0, t1, t2, t3;
        {
            const float s0 = bb4 ? sn[0] : mk[0];
            const float s1 = bb4 ? sn[1] : mk[1];
            const float s2 = bb4 ? sn[2] : mk[2];
            const float s3 = bb4 ? sn[3] : mk[3];
            t0 = (bb4 ? mk[0] : sn[0]) + __shfl_xor_sync(0xffffffffu, s0, 16);
            t1 = (bb4 ? mk[1] : sn[1]) + __shfl_xor_sync(0xffffffffu, s1, 16);
            t2 = (bb4 ? mk[2] : sn[2]) + __shfl_xor_sync(0xffffffffu, s2, 16);
            t3 = (bb4 ? mk[3] : sn[3]) + __shfl_xor_sync(0xffffffffu, s3, 16);
        }
        float u0, u1;
        {
            const float s0 = bb3 ? t0 : t2;
            const float s1 = bb3 ? t1 : t3;
            u0 = (bb3 ? t2 : t0) + __shfl_xor_sync(0xffffffffu, s0, 8);
            u1 = (bb3 ? t3 : t1) + __shfl_xor_sync(0xffffffffu, s1, 8);
        }
        float c;
        {
            const float s0 = bb2 ? u0 : u1;
            c = (bb2 ? u1 : u0) + __shfl_xor_sync(0xffffffffu, s0, 4);
        }
        c += __shfl_xor_sync(0xffffffffu, c, 2);
        c += __shfl_xor_sync(0xffffffffu, c, 1);

        // self-score: plain 5-level tree (independent chain)
#pragma unroll
        for (int o = 16; o; o >>= 1)
            self_part += __shfl_xor_sync(0xffffffffu, self_part, o);

        if ((lane & 3) == 0) {
            const int idx = lane >> 2;            // 0..7
            if (idx < 4) s_nbr[w * SPW + idx] = c;
            else         s_msk[w * SPW + (idx - 4)] = c;
        }
        if (lane == 0) warp_self[w] = self_part;
        __syncthreads();
        // ^ also proves every warp has drained stage[b]: reusable now.

        // ---- early re-issue: row r+2 into buffer b ----
        if (tid == TPB - 32 && r + 2 < rows)
            stage_row(stage_u32 + (uint32_t)(b * ROW_BYTES),
                      x + (size_t)(m + 2) * (L_SEG * F_DIM),
                      mbar_u32 + (uint32_t)(b * 8));

        // ---- phase B: softmax over 32 segments (no max-subtraction) ----
        const float4 ws0 = ((const float4*)warp_self)[0];
        const float4 ws1 = ((const float4*)warp_self)[1];
        const float s_self = ((ws0.x + ws0.y) + (ws0.z + ws0.w))
                           + ((ws1.x + ws1.y) + (ws1.z + ws1.w));
        const float z = s_self + s_nbr[lane];
        float e = (z >= 0.0f) ? z : 0.2f * z;
        e = (s_msk[lane] != 0.0f) ? e : -1e30f;
        const float ex = __expf(e);               // masked -> 0
        float sum = ex;
#pragma unroll
        for (int o = 16; o; o >>= 1)
            sum += __shfl_xor_sync(0xffffffffu, sum, o);
        const float att_lane = ex / sum;

        // ---- attention-weighted recombination (packed) ----
        u64t hlo = 0, hhi = 0;
#pragma unroll
        for (int j = 0; j < SPW; ++j) {
            const float aL = __shfl_sync(0xffffffffu, att_lane, w * SPW + j);
            const u64t aL2 = pk2(aL, aL);
            hlo = fma2(aL2, vlo[j], hlo);
            hhi = fma2(aL2, vhi[j], hhi);
        }
        hp[(w * 32 + lane) * 2 + 0] = hlo;
        hp[(w * 32 + lane) * 2 + 1] = hhi;
        __syncthreads();

        // ---- cross-warp reduce (warp 0, packed) + epilogue + store ----
        if (w == 0) {
            u64t alo = hp[lane * 2 + 0];
            u64t ahi = hp[lane * 2 + 1];
#pragma unroll
            for (int i = 1; i < WARPS; ++i) {
                alo = add2(alo, hp[(i * 32 + lane) * 2 + 0]);
                ahi = add2(ahi, hp[(i * 32 + lane) * 2 + 1]);
            }
            float4 acc;
            upk2(alo, acc.x, acc.y);
            upk2(ahi, acc.z, acc.w);
            acc.x = (acc.x > 0.f) ? acc.x : (__expf(acc.x) - 1.0f);
            acc.y = (acc.y > 0.f) ? acc.y : (__expf(acc.y) - 1.0f);
            acc.z = (acc.z > 0.f) ? acc.z : (__expf(acc.z) - 1.0f);
            acc.w = (acc.w > 0.f) ? acc.w : (__expf(acc.w) - 1.0f);
            ((float4*)(out + (size_t)m * F_DIM))[lane] = acc;
        }
    }
}

extern "C" void kernel_launch(void* const* d_in, const int* in_sizes, int n_in,
                              void* d_out, int out_size)
{
    const float* x = (const float*)d_in[0];
    const float* a = (const float*)d_in[1];
    float* out = (float*)d_out;

    // Shapes from element counts (capture-safe):
    //   in_sizes[0] = M*L*F, in_sizes[1] = F*(L+1), out_size = M*F
    const long long total = in_sizes[0];
    const int L = (int)(total / (long long)out_size);      // 32
    const int F = in_sizes[1] / (L + 1);                   // 128
    const int M = out_size / F;                            // 50000
    (void)L; (void)F;

    const int grid = (M + ROWS_PER_CTA - 1) / ROWS_PER_CTA;
    gat_row_kernel<<<grid, TPB>>>(x, a, out, M);
}